// round 4
// baseline (speedup 1.0000x reference)
#include <cuda_runtime.h>

// ---------------------------------------------------------------------------
// RModel_29257317221019: fused cos-MLP deform (3->32->32->32->3) + trilinear
// sample from 256^3 volume. 2 points per thread via packed f32x2 (FFMA2),
// weights duplicated-packed in SMEM, fetched as LDS.128 (2 FFMA2 per load).
// ---------------------------------------------------------------------------

typedef unsigned long long u64;

__device__ __forceinline__ u64 pk2(float lo, float hi) {
    u64 r; asm("mov.b64 %0, {%1, %2};" : "=l"(r) : "f"(lo), "f"(hi)); return r;
}
__device__ __forceinline__ void upk2(u64 v, float& lo, float& hi) {
    asm("mov.b64 {%0, %1}, %2;" : "=f"(lo), "=f"(hi) : "l"(v));
}
__device__ __forceinline__ u64 ffma2(u64 a, u64 b, u64 c) {
    u64 r; asm("fma.rn.f32x2 %0, %1, %2, %3;" : "=l"(r) : "l"(a), "l"(b), "l"(c)); return r;
}
__device__ __forceinline__ u64 add2(u64 a, u64 b) {
    u64 r; asm("add.rn.f32x2 %0, %1, %2;" : "=l"(r) : "l"(a), "l"(b)); return r;
}
__device__ __forceinline__ u64 cos2(u64 v) {
    float lo, hi; upk2(v, lo, hi);
    return pk2(__cosf(lo), __cosf(hi));
}
__device__ __forceinline__ ulonglong2 ld2(const u64* p) {
    return *reinterpret_cast<const ulonglong2*>(p);
}

// Shared layout (u64 entries, weights duplicated into both f32x2 halves).
// All vector-load bases are even indices (16B aligned).
#define OFF_W1  0       // [3][32]  = 96
#define OFF_B1  96      // 32
#define OFF_W2  128     // [32][32] = 1024  (k*32+d)
#define OFF_B2  1152    // 32
#define OFF_W3  1184    // [32][32] = 1024
#define OFF_B3  2208    // 32
#define OFF_WFT 2240    // [3][32]  = 96   (transposed: j*32+k)
#define OFF_BF  2336    // 3
#define SW_TOTAL 2339

__global__ __launch_bounds__(256, 1)
void deform_sample_kernel(
    const float* __restrict__ x,
    const float* __restrict__ W1, const float* __restrict__ b1,
    const float* __restrict__ W2, const float* __restrict__ b2,
    const float* __restrict__ W3, const float* __restrict__ b3,
    const float* __restrict__ Wf, const float* __restrict__ bf,
    const float* __restrict__ vol,
    float* __restrict__ out,
    int npairs)
{
    __shared__ __align__(16) u64 sw[SW_TOTAL];

    // Cooperative weight fill (duplicated into both halves)
    {
        int tid = threadIdx.x;
        for (int i = tid; i < 96;   i += 256) { float v = W1[i]; sw[OFF_W1 + i] = pk2(v, v); }
        for (int i = tid; i < 32;   i += 256) { float v = b1[i]; sw[OFF_B1 + i] = pk2(v, v); }
        for (int i = tid; i < 1024; i += 256) { float v = W2[i]; sw[OFF_W2 + i] = pk2(v, v); }
        for (int i = tid; i < 32;   i += 256) { float v = b2[i]; sw[OFF_B2 + i] = pk2(v, v); }
        for (int i = tid; i < 1024; i += 256) { float v = W3[i]; sw[OFF_W3 + i] = pk2(v, v); }
        for (int i = tid; i < 32;   i += 256) { float v = b3[i]; sw[OFF_B3 + i] = pk2(v, v); }
        // Wf is [32][3] (k*3+j); store transposed [j][k]
        for (int i = tid; i < 96;   i += 256) {
            int j = i >> 5, k = i & 31;
            float v = Wf[k * 3 + j];
            sw[OFF_WFT + i] = pk2(v, v);
        }
        for (int i = tid; i < 3;    i += 256) { float v = bf[i]; sw[OFF_BF + i] = pk2(v, v); }
    }
    __syncthreads();

    int t = blockIdx.x * blockDim.x + threadIdx.x;
    if (t >= npairs) return;

    // Two consecutive points (x layout: 4 floats/point, coords in [0:3])
    const float4* x4 = reinterpret_cast<const float4*>(x);
    float4 A = x4[2 * t + 0];
    float4 B = x4[2 * t + 1];
    u64 c0 = pk2(A.x, B.x);
    u64 c1 = pk2(A.y, B.y);
    u64 c2 = pk2(A.z, B.z);

    u64 h[32];
    u64 acc[32];

    // ---- Layer 1: h = cos(c @ W1 + b1), vectorized over output pairs ----
#pragma unroll
    for (int d = 0; d < 32; d += 2) {
        ulonglong2 bb = ld2(&sw[OFF_B1 + d]);
        ulonglong2 w0 = ld2(&sw[OFF_W1 + 0 * 32 + d]);
        ulonglong2 w1 = ld2(&sw[OFF_W1 + 1 * 32 + d]);
        ulonglong2 w2 = ld2(&sw[OFF_W1 + 2 * 32 + d]);
        u64 a0 = ffma2(c0, w0.x, bb.x);
        u64 a1 = ffma2(c0, w0.y, bb.y);
        a0 = ffma2(c1, w1.x, a0);
        a1 = ffma2(c1, w1.y, a1);
        a0 = ffma2(c2, w2.x, a0);
        a1 = ffma2(c2, w2.y, a1);
        h[d]     = cos2(a0);
        h[d + 1] = cos2(a1);
    }

    // ---- Layer 2: g = cos(h @ W2 + b2); k-outer, d-inner, LDS.128 ----
#pragma unroll
    for (int d = 0; d < 32; d += 2) {
        ulonglong2 bb = ld2(&sw[OFF_B2 + d]);
        acc[d] = bb.x; acc[d + 1] = bb.y;
    }
#pragma unroll
    for (int k = 0; k < 32; k++) {
        u64 hk = h[k];
#pragma unroll
        for (int d = 0; d < 32; d += 2) {
            ulonglong2 w = ld2(&sw[OFF_W2 + k * 32 + d]);
            acc[d]     = ffma2(hk, w.x, acc[d]);
            acc[d + 1] = ffma2(hk, w.y, acc[d + 1]);
        }
    }
#pragma unroll
    for (int d = 0; d < 32; d++) h[d] = cos2(acc[d]);   // h now holds g

    // ---- Layer 3: h = cos(g @ W3 + b3) ----
#pragma unroll
    for (int d = 0; d < 32; d += 2) {
        ulonglong2 bb = ld2(&sw[OFF_B3 + d]);
        acc[d] = bb.x; acc[d + 1] = bb.y;
    }
#pragma unroll
    for (int k = 0; k < 32; k++) {
        u64 gk = h[k];
#pragma unroll
        for (int d = 0; d < 32; d += 2) {
            ulonglong2 w = ld2(&sw[OFF_W3 + k * 32 + d]);
            acc[d]     = ffma2(gk, w.x, acc[d]);
            acc[d + 1] = ffma2(gk, w.y, acc[d + 1]);
        }
    }
#pragma unroll
    for (int d = 0; d < 32; d++) h[d] = cos2(acc[d]);

    // ---- Final: coord = c + 5 * (h @ Wf + bf), Wf transposed [j][k] ----
    const u64 FIVE = pk2(5.0f, 5.0f);
    u64 cin[3] = { c0, c1, c2 };
    u64 pc[3];
#pragma unroll
    for (int j = 0; j < 3; j++) {
        u64 e0 = 0ull, e1 = 0ull, e2 = 0ull, e3 = 0ull;  // 0 bits == (0.0f,0.0f)
#pragma unroll
        for (int k = 0; k < 32; k += 4) {
            ulonglong2 wa = ld2(&sw[OFF_WFT + j * 32 + k]);
            ulonglong2 wb = ld2(&sw[OFF_WFT + j * 32 + k + 2]);
            e0 = ffma2(h[k],     wa.x, e0);
            e1 = ffma2(h[k + 1], wa.y, e1);
            e2 = ffma2(h[k + 2], wb.x, e2);
            e3 = ffma2(h[k + 3], wb.y, e3);
        }
        u64 s = add2(add2(e0, e1), add2(e2, e3));
        s = add2(s, sw[OFF_BF + j]);
        pc[j] = ffma2(FIVE, s, cin[j]);
    }

    // ---- Trilinear sample (scalar per point) ----
    float px[2], py[2], pz[2];
    upk2(pc[0], px[0], px[1]);
    upk2(pc[1], py[0], py[1]);
    upk2(pc[2], pz[0], pz[1]);

    float res[2];
#pragma unroll
    for (int s = 0; s < 2; s++) {
        float cx = fminf(fmaxf(px[s], 0.0f), 255.0f);
        float cy = fminf(fmaxf(py[s], 0.0f), 255.0f);
        float cz = fminf(fmaxf(pz[s], 0.0f), 255.0f);

        float fx0 = floorf(cx), fy0 = floorf(cy), fz0 = floorf(cz);
        int ix0 = (int)fx0, iy0 = (int)fy0, iz0 = (int)fz0;
        int ix1 = min(ix0 + 1, 255);
        int iy1 = min(iy0 + 1, 255);
        int iz1 = min(iz0 + 1, 255);

        float fx = cx - fx0, fy = cy - fy0, fz = cz - fz0;
        float gx = 1.0f - fx, gy = 1.0f - fy, gz = 1.0f - fz;

        int X0 = ix0 << 16, X1 = ix1 << 16;
        int Y0 = iy0 << 8,  Y1 = iy1 << 8;

        float v000 = __ldg(vol + (X0 + Y0 + iz0));
        float v100 = __ldg(vol + (X1 + Y0 + iz0));
        float v010 = __ldg(vol + (X0 + Y1 + iz0));
        float v001 = __ldg(vol + (X0 + Y0 + iz1));
        float v110 = __ldg(vol + (X1 + Y1 + iz0));
        float v101 = __ldg(vol + (X1 + Y0 + iz1));
        float v011 = __ldg(vol + (X0 + Y1 + iz1));
        float v111 = __ldg(vol + (X1 + Y1 + iz1));

        float r;
        r  = v000 * (gx * gy * gz);
        r += v100 * (fx * gy * gz);
        r += v010 * (gx * fy * gz);
        r += v001 * (gx * gy * fz);
        r += v110 * (fx * fy * gz);
        r += v101 * (fx * gy * fz);
        r += v011 * (gx * fy * fz);
        r += v111 * (fx * fy * fz);
        res[s] = r;
    }

    float2 o;
    o.x = res[0];
    o.y = res[1];
    reinterpret_cast<float2*>(out)[t] = o;
}

extern "C" void kernel_launch(void* const* d_in, const int* in_sizes, int n_in,
                              void* d_out, int out_size) {
    const float* x   = (const float*)d_in[0];
    const float* W1  = (const float*)d_in[1];
    const float* b1  = (const float*)d_in[2];
    const float* W2  = (const float*)d_in[3];
    const float* b2  = (const float*)d_in[4];
    const float* W3  = (const float*)d_in[5];
    const float* b3  = (const float*)d_in[6];
    const float* Wf  = (const float*)d_in[7];
    const float* bf  = (const float*)d_in[8];
    const float* vol = (const float*)d_in[9];
    float* out = (float*)d_out;

    int npts = out_size;           // 2,097,152 points
    int npairs = npts / 2;         // 2 points per thread
    int block = 256;
    int grid = (npairs + block - 1) / block;

    deform_sample_kernel<<<grid, block>>>(x, W1, b1, W2, b2, W3, b3, Wf, bf,
                                          vol, out, npairs);
}

// round 5
// speedup vs baseline: 1.1653x; 1.1653x over previous
#include <cuda_runtime.h>

// ---------------------------------------------------------------------------
// RModel_29257317221019: fused cos-MLP deform (3->32->32->32->3) + trilinear
// sample from 256^3 volume.
// 1 point per thread; f32x2 packing over OUTPUT pairs (d,d+1):
//   - state = acc[16] u64 + h[32] f32 = 64 regs  -> 2 CTAs/SM (16 warps)
//   - weights stored RAW in smem; ld.shared.v2.b64 gives two (w_d,w_d+1)
//     f32x2 operands per 16B load -> weight wavefronts halved
//   - activation duplicated per k with one mov.b64 {h,h}
// ---------------------------------------------------------------------------

typedef unsigned long long u64;

__device__ __forceinline__ u64 pk2(float lo, float hi) {
    u64 r; asm("mov.b64 %0, {%1, %2};" : "=l"(r) : "f"(lo), "f"(hi)); return r;
}
__device__ __forceinline__ void upk2(u64 v, float& lo, float& hi) {
    asm("mov.b64 {%0, %1}, %2;" : "=f"(lo), "=f"(hi) : "l"(v));
}
__device__ __forceinline__ u64 dup2(float v) {
    u64 r; asm("mov.b64 %0, {%1, %1};" : "=l"(r) : "f"(v)); return r;
}
__device__ __forceinline__ u64 ffma2(u64 a, u64 b, u64 c) {
    u64 r; asm("fma.rn.f32x2 %0, %1, %2, %3;" : "=l"(r) : "l"(a), "l"(b), "l"(c)); return r;
}
// 16B shared load -> two u64 (each = two consecutive f32 = one f32x2 operand)
__device__ __forceinline__ void lds_v2b64(unsigned addr, u64& a, u64& b) {
    asm("ld.shared.v2.b64 {%0, %1}, [%2];" : "=l"(a), "=l"(b) : "r"(addr));
}

// Shared float layout (all section bases multiple of 4 floats = 16B aligned)
#define OFF_W1   0      // [3][32]  = 96   (c*32+d)
#define OFF_B1   96     // 32
#define OFF_W2   128    // [32][32] = 1024 (k*32+d)
#define OFF_B2   1152   // 32
#define OFF_W3   1184   // [32][32] = 1024
#define OFF_B3   2208   // 32
#define OFF_WF4  2240   // [32][4]  = 128  (k*4+j, j=3 is zero pad)
#define OFF_BF   2368   // 4 (padded)
#define SW_TOTAL 2372

__global__ __launch_bounds__(256, 2)
void deform_sample_kernel(
    const float* __restrict__ x,
    const float* __restrict__ W1, const float* __restrict__ b1,
    const float* __restrict__ W2, const float* __restrict__ b2,
    const float* __restrict__ W3, const float* __restrict__ b3,
    const float* __restrict__ Wf, const float* __restrict__ bf,
    const float* __restrict__ vol,
    float* __restrict__ out,
    int npts)
{
    __shared__ __align__(16) float ws[SW_TOTAL];

    // Cooperative fill of raw weights
    {
        int tid = threadIdx.x;
        for (int i = tid; i < 96;   i += 256) ws[OFF_W1 + i] = W1[i];
        for (int i = tid; i < 32;   i += 256) ws[OFF_B1 + i] = b1[i];
        for (int i = tid; i < 1024; i += 256) ws[OFF_W2 + i] = W2[i];
        for (int i = tid; i < 32;   i += 256) ws[OFF_B2 + i] = b2[i];
        for (int i = tid; i < 1024; i += 256) ws[OFF_W3 + i] = W3[i];
        for (int i = tid; i < 32;   i += 256) ws[OFF_B3 + i] = b3[i];
        for (int i = tid; i < 128;  i += 256) {
            int k = i >> 2, j = i & 3;
            ws[OFF_WF4 + i] = (j < 3) ? Wf[k * 3 + j] : 0.0f;
        }
        for (int i = tid; i < 4;    i += 256) ws[OFF_BF + i] = (i < 3) ? bf[i] : 0.0f;
    }
    __syncthreads();

    unsigned sbase;
    {
        void* p = (void*)ws;
        sbase = (unsigned)__cvta_generic_to_shared(p);
    }

    int t = blockIdx.x * blockDim.x + threadIdx.x;
    if (t >= npts) return;

    // One point per thread (x layout: 4 floats/point, coords in [0:3])
    float4 X = reinterpret_cast<const float4*>(x)[t];
    u64 cd0 = dup2(X.x);
    u64 cd1 = dup2(X.y);
    u64 cd2 = dup2(X.z);

    float h[32];
    u64 acc[16];     // d-pair accumulators

    // ---- Layer 1: h = cos(c @ W1 + b1) ----
#pragma unroll
    for (int q = 0; q < 8; q++) {            // q covers d = 4q .. 4q+3
        u64 b0, b1p;
        lds_v2b64(sbase + (OFF_B1 + 4 * q) * 4, b0, b1p);
        u64 a0 = b0, a1 = b1p;
#pragma unroll
        for (int c = 0; c < 3; c++) {
            u64 w0, w1p;
            lds_v2b64(sbase + (OFF_W1 + c * 32 + 4 * q) * 4, w0, w1p);
            u64 cc = (c == 0) ? cd0 : (c == 1) ? cd1 : cd2;
            a0 = ffma2(cc, w0, a0);
            a1 = ffma2(cc, w1p, a1);
        }
        float lo, hi;
        upk2(a0, lo, hi); h[4 * q]     = __cosf(lo); h[4 * q + 1] = __cosf(hi);
        upk2(a1, lo, hi); h[4 * q + 2] = __cosf(lo); h[4 * q + 3] = __cosf(hi);
    }

    // ---- Layer 2: h = cos(h @ W2 + b2) ----
#pragma unroll
    for (int q = 0; q < 8; q++) {
        u64 b0, b1p;
        lds_v2b64(sbase + (OFF_B2 + 4 * q) * 4, b0, b1p);
        acc[2 * q] = b0; acc[2 * q + 1] = b1p;
    }
#pragma unroll
    for (int k = 0; k < 32; k++) {
        u64 hd = dup2(h[k]);
        unsigned row = sbase + (OFF_W2 + k * 32) * 4;
#pragma unroll
        for (int q = 0; q < 8; q++) {
            u64 w0, w1p;
            lds_v2b64(row + 16 * q, w0, w1p);
            acc[2 * q]     = ffma2(hd, w0, acc[2 * q]);
            acc[2 * q + 1] = ffma2(hd, w1p, acc[2 * q + 1]);
        }
    }
#pragma unroll
    for (int p = 0; p < 16; p++) {
        float lo, hi; upk2(acc[p], lo, hi);
        h[2 * p] = __cosf(lo); h[2 * p + 1] = __cosf(hi);
    }

    // ---- Layer 3: h = cos(h @ W3 + b3) ----
#pragma unroll
    for (int q = 0; q < 8; q++) {
        u64 b0, b1p;
        lds_v2b64(sbase + (OFF_B3 + 4 * q) * 4, b0, b1p);
        acc[2 * q] = b0; acc[2 * q + 1] = b1p;
    }
#pragma unroll
    for (int k = 0; k < 32; k++) {
        u64 hd = dup2(h[k]);
        unsigned row = sbase + (OFF_W3 + k * 32) * 4;
#pragma unroll
        for (int q = 0; q < 8; q++) {
            u64 w0, w1p;
            lds_v2b64(row + 16 * q, w0, w1p);
            acc[2 * q]     = ffma2(hd, w0, acc[2 * q]);
            acc[2 * q + 1] = ffma2(hd, w1p, acc[2 * q + 1]);
        }
    }
#pragma unroll
    for (int p = 0; p < 16; p++) {
        float lo, hi; upk2(acc[p], lo, hi);
        h[2 * p] = __cosf(lo); h[2 * p + 1] = __cosf(hi);
    }

    // ---- Final: coord = c + 5 * (h @ Wf + bf)  (Wf padded to [32][4]) ----
    u64 e01, e2p;
    lds_v2b64(sbase + OFF_BF * 4, e01, e2p);   // (bf0,bf1), (bf2, 0)
#pragma unroll
    for (int k = 0; k < 32; k++) {
        u64 hd = dup2(h[k]);
        u64 w01, w2x;
        lds_v2b64(sbase + (OFF_WF4 + k * 4) * 4, w01, w2x);
        e01 = ffma2(hd, w01, e01);
        e2p = ffma2(hd, w2x, e2p);   // hi half accumulates h*0 = 0
    }
    float f0, f1, f2, junk;
    upk2(e01, f0, f1);
    upk2(e2p, f2, junk);
    float px = fmaf(5.0f, f0, X.x);
    float py = fmaf(5.0f, f1, X.y);
    float pz = fmaf(5.0f, f2, X.z);

    // ---- Trilinear sample ----
    float cx = fminf(fmaxf(px, 0.0f), 255.0f);
    float cy = fminf(fmaxf(py, 0.0f), 255.0f);
    float cz = fminf(fmaxf(pz, 0.0f), 255.0f);

    float fx0 = floorf(cx), fy0 = floorf(cy), fz0 = floorf(cz);
    int ix0 = (int)fx0, iy0 = (int)fy0, iz0 = (int)fz0;
    int ix1 = min(ix0 + 1, 255);
    int iy1 = min(iy0 + 1, 255);
    int iz1 = min(iz0 + 1, 255);

    float fx = cx - fx0, fy = cy - fy0, fz = cz - fz0;
    float gx = 1.0f - fx, gy = 1.0f - fy, gz = 1.0f - fz;

    int X0 = ix0 << 16, X1 = ix1 << 16;
    int Y0 = iy0 << 8,  Y1 = iy1 << 8;

    float v000 = __ldg(vol + (X0 + Y0 + iz0));
    float v100 = __ldg(vol + (X1 + Y0 + iz0));
    float v010 = __ldg(vol + (X0 + Y1 + iz0));
    float v001 = __ldg(vol + (X0 + Y0 + iz1));
    float v110 = __ldg(vol + (X1 + Y1 + iz0));
    float v101 = __ldg(vol + (X1 + Y0 + iz1));
    float v011 = __ldg(vol + (X0 + Y1 + iz1));
    float v111 = __ldg(vol + (X1 + Y1 + iz1));

    float r;
    r  = v000 * (gx * gy * gz);
    r += v100 * (fx * gy * gz);
    r += v010 * (gx * fy * gz);
    r += v001 * (gx * gy * fz);
    r += v110 * (fx * fy * gz);
    r += v101 * (fx * gy * fz);
    r += v011 * (gx * fy * fz);
    r += v111 * (fx * fy * fz);

    out[t] = r;
}

extern "C" void kernel_launch(void* const* d_in, const int* in_sizes, int n_in,
                              void* d_out, int out_size) {
    const float* x   = (const float*)d_in[0];
    const float* W1  = (const float*)d_in[1];
    const float* b1  = (const float*)d_in[2];
    const float* W2  = (const float*)d_in[3];
    const float* b2  = (const float*)d_in[4];
    const float* W3  = (const float*)d_in[5];
    const float* b3  = (const float*)d_in[6];
    const float* Wf  = (const float*)d_in[7];
    const float* bf  = (const float*)d_in[8];
    const float* vol = (const float*)d_in[9];
    float* out = (float*)d_out;

    int npts = out_size;           // 2,097,152 points, 1 point per thread
    int block = 256;
    int grid = (npts + block - 1) / block;

    deform_sample_kernel<<<grid, block>>>(x, W1, b1, W2, b2, W3, b3, Wf, bf,
                                          vol, out, npts);
}

// round 6
// speedup vs baseline: 1.7084x; 1.4661x over previous
#include <cuda_runtime.h>

// ---------------------------------------------------------------------------
// RModel_29257317221019: fused cos-MLP deform (3->32->32->32->3) + trilinear
// sample from 256^3 volume.
// 2 points per thread; f32x2 packing over OUTPUT pairs (d,d+1):
//   - one broadcast LDS.128 (raw weights w[k][d..d+3]) feeds 4 FFMA2
//     (2 d-pairs x 2 points)  -> weight L1 wavefronts per point halved vs R5
//   - activations duplicated on the fly (mov.b64 {h,h}, ALU pipe ~3% busy)
//   - state: acc[16]x2 u64 + h[32]x2 f32 ~ 128 regs -> 128-thr blocks, 3 CTAs
// ---------------------------------------------------------------------------

typedef unsigned long long u64;

__device__ __forceinline__ void upk2(u64 v, float& lo, float& hi) {
    asm("mov.b64 {%0, %1}, %2;" : "=f"(lo), "=f"(hi) : "l"(v));
}
__device__ __forceinline__ u64 dup2(float v) {
    u64 r; asm("mov.b64 %0, {%1, %1};" : "=l"(r) : "f"(v)); return r;
}
__device__ __forceinline__ u64 ffma2(u64 a, u64 b, u64 c) {
    u64 r; asm("fma.rn.f32x2 %0, %1, %2, %3;" : "=l"(r) : "l"(a), "l"(b), "l"(c)); return r;
}
// 16B shared load -> two u64 (each = two consecutive f32 = one f32x2 operand)
__device__ __forceinline__ void lds_v2b64(unsigned addr, u64& a, u64& b) {
    asm("ld.shared.v2.b64 {%0, %1}, [%2];" : "=l"(a), "=l"(b) : "r"(addr));
}
__device__ __forceinline__ u64 lds_b64(unsigned addr) {
    u64 a; asm("ld.shared.b64 %0, [%1];" : "=l"(a) : "r"(addr)); return a;
}

// Shared float layout (all section bases multiple of 4 floats = 16B aligned)
#define OFF_W1   0      // [3][32]  = 96   (c*32+d)
#define OFF_B1   96     // 32
#define OFF_W2   128    // [32][32] = 1024 (k*32+d)
#define OFF_B2   1152   // 32
#define OFF_W3   1184   // [32][32] = 1024
#define OFF_B3   2208   // 32
#define OFF_WF4  2240   // [32][4]  = 128  (k*4+j, j=3 zero pad)
#define OFF_BF   2368   // 4 (padded)
#define SW_TOTAL 2372

#define BLK 128

__global__ __launch_bounds__(BLK, 3)
void deform_sample_kernel(
    const float* __restrict__ x,
    const float* __restrict__ W1, const float* __restrict__ b1,
    const float* __restrict__ W2, const float* __restrict__ b2,
    const float* __restrict__ W3, const float* __restrict__ b3,
    const float* __restrict__ Wf, const float* __restrict__ bf,
    const float* __restrict__ vol,
    float* __restrict__ out,
    int npairs)
{
    __shared__ __align__(16) float ws[SW_TOTAL];

    // Cooperative fill of raw weights
    {
        int tid = threadIdx.x;
        for (int i = tid; i < 96;   i += BLK) ws[OFF_W1 + i] = W1[i];
        for (int i = tid; i < 32;   i += BLK) ws[OFF_B1 + i] = b1[i];
        for (int i = tid; i < 1024; i += BLK) ws[OFF_W2 + i] = W2[i];
        for (int i = tid; i < 32;   i += BLK) ws[OFF_B2 + i] = b2[i];
        for (int i = tid; i < 1024; i += BLK) ws[OFF_W3 + i] = W3[i];
        for (int i = tid; i < 32;   i += BLK) ws[OFF_B3 + i] = b3[i];
        for (int i = tid; i < 128;  i += BLK) {
            int k = i >> 2, j = i & 3;
            ws[OFF_WF4 + i] = (j < 3) ? Wf[k * 3 + j] : 0.0f;
        }
        for (int i = tid; i < 4;    i += BLK) ws[OFF_BF + i] = (i < 3) ? bf[i] : 0.0f;
    }
    __syncthreads();

    unsigned sbase = (unsigned)__cvta_generic_to_shared((void*)ws);

    int t = blockIdx.x * blockDim.x + threadIdx.x;
    if (t >= npairs) return;

    // Two consecutive points (x layout: 4 floats/point, coords in [0:3])
    const float4* x4 = reinterpret_cast<const float4*>(x);
    float4 XA = x4[2 * t + 0];
    float4 XB = x4[2 * t + 1];

    float hA[32], hB[32];
    u64 aA[16], aB[16];

    // ---- Layer 1: h = cos(c @ W1 + b1) ----
    {
        u64 cA0 = dup2(XA.x), cA1 = dup2(XA.y), cA2 = dup2(XA.z);
        u64 cB0 = dup2(XB.x), cB1 = dup2(XB.y), cB2 = dup2(XB.z);
#pragma unroll
        for (int q = 0; q < 8; q++) {        // q covers d = 4q .. 4q+3
            u64 b0, b1p;
            lds_v2b64(sbase + (OFF_B1 + 4 * q) * 4, b0, b1p);
            u64 pA0 = b0, pA1 = b1p, pB0 = b0, pB1 = b1p;
#pragma unroll
            for (int c = 0; c < 3; c++) {
                u64 w0, w1p;
                lds_v2b64(sbase + (OFF_W1 + c * 32 + 4 * q) * 4, w0, w1p);
                u64 ca = (c == 0) ? cA0 : (c == 1) ? cA1 : cA2;
                u64 cb = (c == 0) ? cB0 : (c == 1) ? cB1 : cB2;
                pA0 = ffma2(ca, w0, pA0);
                pA1 = ffma2(ca, w1p, pA1);
                pB0 = ffma2(cb, w0, pB0);
                pB1 = ffma2(cb, w1p, pB1);
            }
            float lo, hi;
            upk2(pA0, lo, hi); hA[4*q]   = __cosf(lo); hA[4*q+1] = __cosf(hi);
            upk2(pA1, lo, hi); hA[4*q+2] = __cosf(lo); hA[4*q+3] = __cosf(hi);
            upk2(pB0, lo, hi); hB[4*q]   = __cosf(lo); hB[4*q+1] = __cosf(hi);
            upk2(pB1, lo, hi); hB[4*q+2] = __cosf(lo); hB[4*q+3] = __cosf(hi);
        }
    }

    // ---- Layer 2: h = cos(h @ W2 + b2) ----
#pragma unroll
    for (int q = 0; q < 8; q++) {
        u64 b0, b1p;
        lds_v2b64(sbase + (OFF_B2 + 4 * q) * 4, b0, b1p);
        aA[2*q] = b0; aA[2*q+1] = b1p;
        aB[2*q] = b0; aB[2*q+1] = b1p;
    }
#pragma unroll
    for (int k = 0; k < 32; k++) {
        u64 dA = dup2(hA[k]);
        u64 dB = dup2(hB[k]);
        unsigned row = sbase + (OFF_W2 + k * 32) * 4;
#pragma unroll
        for (int q = 0; q < 8; q++) {
            u64 w0, w1p;
            lds_v2b64(row + 16 * q, w0, w1p);
            aA[2*q]   = ffma2(dA, w0, aA[2*q]);
            aA[2*q+1] = ffma2(dA, w1p, aA[2*q+1]);
            aB[2*q]   = ffma2(dB, w0, aB[2*q]);
            aB[2*q+1] = ffma2(dB, w1p, aB[2*q+1]);
        }
    }
#pragma unroll
    for (int p = 0; p < 16; p++) {
        float lo, hi;
        upk2(aA[p], lo, hi); hA[2*p] = __cosf(lo); hA[2*p+1] = __cosf(hi);
        upk2(aB[p], lo, hi); hB[2*p] = __cosf(lo); hB[2*p+1] = __cosf(hi);
    }

    // ---- Layer 3: h = cos(h @ W3 + b3) ----
#pragma unroll
    for (int q = 0; q < 8; q++) {
        u64 b0, b1p;
        lds_v2b64(sbase + (OFF_B3 + 4 * q) * 4, b0, b1p);
        aA[2*q] = b0; aA[2*q+1] = b1p;
        aB[2*q] = b0; aB[2*q+1] = b1p;
    }
#pragma unroll
    for (int k = 0; k < 32; k++) {
        u64 dA = dup2(hA[k]);
        u64 dB = dup2(hB[k]);
        unsigned row = sbase + (OFF_W3 + k * 32) * 4;
#pragma unroll
        for (int q = 0; q < 8; q++) {
            u64 w0, w1p;
            lds_v2b64(row + 16 * q, w0, w1p);
            aA[2*q]   = ffma2(dA, w0, aA[2*q]);
            aA[2*q+1] = ffma2(dA, w1p, aA[2*q+1]);
            aB[2*q]   = ffma2(dB, w0, aB[2*q]);
            aB[2*q+1] = ffma2(dB, w1p, aB[2*q+1]);
        }
    }
#pragma unroll
    for (int p = 0; p < 16; p++) {
        float lo, hi;
        upk2(aA[p], lo, hi); hA[2*p] = __cosf(lo); hA[2*p+1] = __cosf(hi);
        upk2(aB[p], lo, hi); hB[2*p] = __cosf(lo); hB[2*p+1] = __cosf(hi);
    }

    // ---- Final: coord = c + 5 * (h @ Wf + bf)  (Wf padded to [32][4]) ----
    float pxy[2][3];
    {
        u64 bf01 = lds_b64(sbase + OFF_BF * 4);
        u64 bf2x = lds_b64(sbase + (OFF_BF + 2) * 4);
        u64 eA01 = bf01, eA2 = bf2x, eB01 = bf01, eB2 = bf2x;
#pragma unroll
        for (int k = 0; k < 32; k++) {
            u64 w01, w2x;
            lds_v2b64(sbase + (OFF_WF4 + k * 4) * 4, w01, w2x);
            u64 dA = dup2(hA[k]);
            u64 dB = dup2(hB[k]);
            eA01 = ffma2(dA, w01, eA01);
            eA2  = ffma2(dA, w2x, eA2);
            eB01 = ffma2(dB, w01, eB01);
            eB2  = ffma2(dB, w2x, eB2);
        }
        float f0, f1, f2, jk;
        upk2(eA01, f0, f1); upk2(eA2, f2, jk);
        pxy[0][0] = fmaf(5.0f, f0, XA.x);
        pxy[0][1] = fmaf(5.0f, f1, XA.y);
        pxy[0][2] = fmaf(5.0f, f2, XA.z);
        upk2(eB01, f0, f1); upk2(eB2, f2, jk);
        pxy[1][0] = fmaf(5.0f, f0, XB.x);
        pxy[1][1] = fmaf(5.0f, f1, XB.y);
        pxy[1][2] = fmaf(5.0f, f2, XB.z);
    }

    // ---- Trilinear sample (scalar per point) ----
    float res[2];
#pragma unroll
    for (int s = 0; s < 2; s++) {
        float cx = fminf(fmaxf(pxy[s][0], 0.0f), 255.0f);
        float cy = fminf(fmaxf(pxy[s][1], 0.0f), 255.0f);
        float cz = fminf(fmaxf(pxy[s][2], 0.0f), 255.0f);

        float fx0 = floorf(cx), fy0 = floorf(cy), fz0 = floorf(cz);
        int ix0 = (int)fx0, iy0 = (int)fy0, iz0 = (int)fz0;
        int ix1 = min(ix0 + 1, 255);
        int iy1 = min(iy0 + 1, 255);
        int iz1 = min(iz0 + 1, 255);

        float fx = cx - fx0, fy = cy - fy0, fz = cz - fz0;
        float gx = 1.0f - fx, gy = 1.0f - fy, gz = 1.0f - fz;

        int X0 = ix0 << 16, X1 = ix1 << 16;
        int Y0 = iy0 << 8,  Y1 = iy1 << 8;

        float v000 = __ldg(vol + (X0 + Y0 + iz0));
        float v100 = __ldg(vol + (X1 + Y0 + iz0));
        float v010 = __ldg(vol + (X0 + Y1 + iz0));
        float v001 = __ldg(vol + (X0 + Y0 + iz1));
        float v110 = __ldg(vol + (X1 + Y1 + iz0));
        float v101 = __ldg(vol + (X1 + Y0 + iz1));
        float v011 = __ldg(vol + (X0 + Y1 + iz1));
        float v111 = __ldg(vol + (X1 + Y1 + iz1));

        float r;
        r  = v000 * (gx * gy * gz);
        r += v100 * (fx * gy * gz);
        r += v010 * (gx * fy * gz);
        r += v001 * (gx * gy * fz);
        r += v110 * (fx * fy * gz);
        r += v101 * (fx * gy * fz);
        r += v011 * (gx * fy * fz);
        r += v111 * (fx * fy * fz);
        res[s] = r;
    }

    float2 o; o.x = res[0]; o.y = res[1];
    reinterpret_cast<float2*>(out)[t] = o;
}

extern "C" void kernel_launch(void* const* d_in, const int* in_sizes, int n_in,
                              void* d_out, int out_size) {
    const float* x   = (const float*)d_in[0];
    const float* W1  = (const float*)d_in[1];
    const float* b1  = (const float*)d_in[2];
    const float* W2  = (const float*)d_in[3];
    const float* b2  = (const float*)d_in[4];
    const float* W3  = (const float*)d_in[5];
    const float* b3  = (const float*)d_in[6];
    const float* Wf  = (const float*)d_in[7];
    const float* bf  = (const float*)d_in[8];
    const float* vol = (const float*)d_in[9];
    float* out = (float*)d_out;

    int npts = out_size;           // 2,097,152 points
    int npairs = npts / 2;         // 2 points per thread
    int grid = (npairs + BLK - 1) / BLK;

    deform_sample_kernel<<<grid, BLK>>>(x, W1, b1, W2, b2, W3, b3, Wf, bf,
                                        vol, out, npairs);
}